// round 4
// baseline (speedup 1.0000x reference)
#include <cuda_runtime.h>
#include <math.h>

#define BB 16
#define HW 65536            // 256*256
#define NPIX (BB*HW)        // 1048576
#define WPR 8               // u32 words per row
#define WPS 2048            // words per sample
#define NWORDS 32768
#define NB 512              // grid size (co-resident: capacity ~888 at 40 regs)
#define TPB 256

// ---- device scratch (allocation-free). Reset by finalize each replay. ----
__device__ unsigned g_posbits[NWORDS];
__device__ unsigned g_t1bits[NWORDS];
__device__ double g_ce;
__device__ int    g_hard_i, g_t_i, g_inter_i;
__device__ double g_res[BB];
__device__ int    g_haspos[BB];
__device__ int    g_hasneg[BB];
__device__ unsigned g_bar1;
__device__ unsigned g_bar2;

// ---------------------------------------------------------------------------
// Fallback: exact min |dx| to differing pixel in one row (bitboard scan).
// ---------------------------------------------------------------------------
__device__ __forceinline__ int row_mindx(const unsigned* __restrict__ row, int j, unsigned inv) {
    int wj = j >> 5, off = j & 31;
    int best = 30000;
    unsigned m = (row[wj] ^ inv) >> off;
    if (m) best = __ffs(m) - 1;
    else {
        for (int w = wj + 1; w < WPR; ++w) {
            unsigned x = row[w] ^ inv;
            if (x) { best = 32 * (w - wj) - off + __ffs(x) - 1; break; }
        }
    }
    unsigned ml = (row[wj] ^ inv) << (31 - off);
    if (ml) { int d = __clz(ml); best = min(best, d); }
    else {
        for (int w = wj - 1; w >= 0; --w) {
            unsigned x = row[w] ^ inv;
            if (x) { int d = j - (32 * w + 31 - __clz(x)); best = min(best, d); break; }
        }
    }
    return best;
}

__device__ double fb_contrib(const unsigned* __restrict__ bp, int i, int j, int mybit,
                             int haspos, int hasneg) {
    float d;
    if (!haspos || !hasneg) {
        d = 1.0e9f;                      // reference BIG: no opposite class exists
    } else {
        unsigned inv = mybit ? 0xffffffffu : 0u;
        int best2 = 1 << 30;
        for (int dy = 0; dy < 256; ++dy) {
            int dy2 = dy * dy;
            if (dy2 >= best2) break;
            int up = i - dy, dn = i + dy;
            if (up >= 0) {
                int dx = row_mindx(bp + up * WPR, j, inv);
                int d2 = dy2 + dx * dx;
                if (d2 < best2) best2 = d2;
            }
            if (dy && dn < 256) {
                int dx = row_mindx(bp + dn * WPR, j, inv);
                int d2 = dy2 + dx * dx;
                if (d2 < best2) best2 = d2;
            }
        }
        d = sqrtf((float)best2);
    }
    return mybit ? -(double)(d - 1.0f) : (double)d;
}

// ---------------------------------------------------------------------------
// Single fused kernel: prep -> grid barrier -> boundary -> finalize
// ---------------------------------------------------------------------------
__global__ __launch_bounds__(TPB)
void k_fused(const float* __restrict__ inp, const int* __restrict__ tgt,
             float* __restrict__ out, int out_size) {
    int tid = threadIdx.x;
    int gt  = blockIdx.x * TPB + tid;
    // ================= Phase 1: mask/t1 bitboards + CE + dice ==============
    {
        int px = gt * 8;                  // 8 consecutive pixels per thread
        int b  = px >> 16;                // block spans 2048 px: single sample
        int hw = px & 65535;

        const float* p0 = inp + (size_t)(b * 2    ) * HW + hw;
        const float* p1 = inp + (size_t)(b * 2 + 1) * HW + hw;
        float4 a0 = *(const float4*)(p0);
        float4 a1 = *(const float4*)(p0 + 4);
        float4 c0 = *(const float4*)(p1);
        float4 c1 = *(const float4*)(p1 + 4);
        int4  t0 = *(const int4*)(tgt + px);
        int4  t1v = *(const int4*)(tgt + px + 4);

        float ces = 0.0f;
        int hard = 0, tcnt = 0, inter = 0;
        unsigned pbyte = 0, tbyte = 0;

        #define ELEM(K, X0, X1, T) {                                   \
            float x0 = (X0), x1 = (X1); int t = (T);                   \
            float m   = fmaxf(x0, x1);                                 \
            float lse = m + log1pf(__expf(-fabsf(x1 - x0)));           \
            ces += lse - ((t == 1) ? x1 : x0);                         \
            int h  = (x1 >= x0);                                       \
            int tt = (t == 1);                                         \
            hard += h; tcnt += tt; inter += (h & tt);                  \
            pbyte |= ((unsigned)(x1 > x0)) << (K);                     \
            tbyte |= ((unsigned)tt) << (K); }

        ELEM(0, a0.x, c0.x, t0.x)  ELEM(1, a0.y, c0.y, t0.y)
        ELEM(2, a0.z, c0.z, t0.z)  ELEM(3, a0.w, c0.w, t0.w)
        ELEM(4, a1.x, c1.x, t1v.x) ELEM(5, a1.y, c1.y, t1v.y)
        ELEM(6, a1.z, c1.z, t1v.z) ELEM(7, a1.w, c1.w, t1v.w)
        #undef ELEM

        __shared__ unsigned char by_p[TPB], by_t[TPB];
        by_p[tid] = (unsigned char)pbyte;
        by_t[tid] = (unsigned char)tbyte;

        double ce = (double)ces;
        int p1c = hard | (tcnt << 16);
        int flags = (pbyte ? 1 : 0) | ((pbyte != 0xffu) ? 2 : 0);
        #pragma unroll
        for (int off = 16; off > 0; off >>= 1) {
            ce    += __shfl_xor_sync(0xffffffffu, ce, off);
            p1c   += __shfl_xor_sync(0xffffffffu, p1c, off);
            inter += __shfl_xor_sync(0xffffffffu, inter, off);
            flags |= __shfl_xor_sync(0xffffffffu, flags, off);
        }
        __shared__ double s_ce[8];
        __shared__ int    s_p1[8], s_in[8], s_fl[8];
        int wid = tid >> 5;
        if ((tid & 31) == 0) { s_ce[wid] = ce; s_p1[wid] = p1c; s_in[wid] = inter; s_fl[wid] = flags; }
        __syncthreads();

        // word assembly: block covers 64 u32 words; word w from 4 bytes
        if (tid < 128) {
            int w = tid & 63;
            const unsigned char* nb = (tid < 64) ? by_p : by_t;
            unsigned v =  (unsigned)nb[4*w]
                       | ((unsigned)nb[4*w+1] << 8)
                       | ((unsigned)nb[4*w+2] << 16)
                       | ((unsigned)nb[4*w+3] << 24);
            unsigned* dst = (tid < 64) ? g_posbits : g_t1bits;
            dst[blockIdx.x * 64 + w] = v;
        }

        if (tid == 0) {
            double bce = 0.0; int bp1 = 0, bin = 0, bfl = 0;
            #pragma unroll
            for (int w = 0; w < 8; ++w) { bce += s_ce[w]; bp1 += s_p1[w]; bin += s_in[w]; bfl |= s_fl[w]; }
            atomicAdd(&g_ce, bce);
            atomicAdd(&g_hard_i,  bp1 & 0xffff);
            atomicAdd(&g_t_i,     bp1 >> 16);
            atomicAdd(&g_inter_i, bin);
            if (bfl & 1) g_haspos[b] = 1;
            if (bfl & 2) g_hasneg[b] = 1;
        }
    }

    // ================= Grid barrier (all NB blocks co-resident) ============
    __syncthreads();
    if (tid == 0) {
        __threadfence();
        atomicAdd(&g_bar1, 1u);
        while (*((volatile unsigned*)&g_bar1) < NB) __nanosleep(64);
        __threadfence();
    }
    __syncthreads();

    // ================= Phase 2: bit-parallel boundary ======================
    double contrib = 0.0;
    int wb = blockIdx.x * 64;             // block owns 64 words (one sample)
    int b2 = wb >> 11;
    if (tid < 64) {
        int wglob = wb + tid;
        int w  = wglob & 2047;
        int i  = w >> 3;
        int wc = w & 7;
        const unsigned* __restrict__ bp = g_posbits + b2 * WPS;
        const unsigned* __restrict__ tp = g_t1bits  + b2 * WPS;

        unsigned lmask = (wc == 0) ? 0xfffffffeu : 0xffffffffu;
        unsigned rmask = (wc == 7) ? 0x7fffffffu : 0xffffffffu;
        unsigned vu = (i > 0)   ? 0xffffffffu : 0u;
        unsigned vd = (i < 255) ? 0xffffffffu : 0u;
        int iu = max(i - 1, 0), id = min(i + 1, 255);

        unsigned P  = bp[i * WPR + wc];
        unsigned L0 = (wc > 0) ? bp[i * WPR + wc - 1] : 0u;
        unsigned R0 = (wc < 7) ? bp[i * WPR + wc + 1] : 0u;
        unsigned Mu = bp[iu * WPR + wc];
        unsigned Lu = (wc > 0) ? bp[iu * WPR + wc - 1] : 0u;
        unsigned Ru = (wc < 7) ? bp[iu * WPR + wc + 1] : 0u;
        unsigned Md = bp[id * WPR + wc];
        unsigned Ld = (wc > 0) ? bp[id * WPR + wc - 1] : 0u;
        unsigned Rd = (wc < 7) ? bp[id * WPR + wc + 1] : 0u;
        unsigned T1 = tp[i * WPR + wc];

        unsigned sm0 = __funnelshift_l(L0, P,  1);
        unsigned sp0 = __funnelshift_r(P,  R0, 1);
        unsigned smu = __funnelshift_l(Lu, Mu, 1);
        unsigned spu = __funnelshift_r(Mu, Ru, 1);
        unsigned smd = __funnelshift_l(Ld, Md, 1);
        unsigned spd = __funnelshift_r(Md, Rd, 1);

        unsigned D1 = ((sm0 ^ P) & lmask) | ((sp0 ^ P) & rmask)
                    | ((Mu ^ P) & vu)     | ((Md ^ P) & vd);
        unsigned D2 = ((((smu ^ P) & lmask) | ((spu ^ P) & rmask)) & vu)
                    | ((((smd ^ P) & lmask) | ((spd ^ P) & rmask)) & vd);

        unsigned A1 = D1 & T1;
        unsigned A2 = D2 & T1 & ~D1;
        int c1n = __popc(A1 & ~P);
        int c2n = __popc(A2 & ~P);
        int c2p = __popc(A2 & P);

        const double SQ2 = (double)1.41421354f;   // f32 sqrt(2): matches reference
        contrib = (double)c1n + (double)c2n * SQ2 - (double)c2p * (SQ2 - 1.0);

        unsigned U = T1 & ~(D1 | D2);             // rare fallback pixels
        if (U) {
            int haspos = g_haspos[b2], hasneg = g_hasneg[b2];
            do {
                int jb = __ffs(U) - 1; U &= U - 1;
                int j = wc * 32 + jb;
                int mybit = (P >> jb) & 1;
                contrib += fb_contrib(bp, i, j, mybit, haspos, hasneg);
            } while (U);
        }
    }

    // block reduce (only first 2 warps carry nonzero)
    #pragma unroll
    for (int off = 16; off > 0; off >>= 1)
        contrib += __shfl_xor_sync(0xffffffffu, contrib, off);
    __shared__ double s_c[2];
    if (tid == 0)  s_c[0] = contrib;
    if (tid == 32) s_c[1] = contrib;
    __syncthreads();

    __shared__ bool s_last;
    if (tid == 0) {
        atomicAdd(&g_res[b2], s_c[0] + s_c[1]);
        __threadfence();
        unsigned tk = atomicAdd(&g_bar2, 1u);
        s_last = (tk == NB - 1);
    }
    __syncthreads();

    // ================= Finalize in last block ==============================
    if (s_last && tid == 0) {
        double ce = g_ce / (double)NPIX;
        double dice = 1.0 - (2.0 * (double)g_inter_i + 1.0)
                          / ((double)g_hard_i + (double)g_t_i + 1.0);
        double lb = 0.0;
        #pragma unroll
        for (int s = 0; s < BB; ++s)
            if (g_haspos[s]) lb += g_res[s] / (double)HW;
        float r = (float)(ce + dice + lb * lb);
        for (int k = 0; k < out_size; ++k) out[k] = r;

        g_ce = 0.0; g_hard_i = 0; g_t_i = 0; g_inter_i = 0;
        #pragma unroll
        for (int s = 0; s < BB; ++s) { g_res[s] = 0.0; g_haspos[s] = 0; g_hasneg[s] = 0; }
        g_bar1 = 0u; g_bar2 = 0u;
    }
}

extern "C" void kernel_launch(void* const* d_in, const int* in_sizes, int n_in,
                              void* d_out, int out_size) {
    const float* inputs  = (const float*)d_in[0];   // (16,2,256,256) f32
    const int*   targets = (const int*)  d_in[1];   // (16,256,256)   i32
    k_fused<<<NB, TPB>>>(inputs, targets, (float*)d_out, out_size);
}

// round 5
// speedup vs baseline: 1.2388x; 1.2388x over previous
#include <cuda_runtime.h>
#include <math.h>

#define BB 16
#define HW 65536            // 256*256
#define NPIX (BB*HW)        // 1048576
#define WPR 8               // u32 words per row
#define WPS 2048            // words per sample
#define NWORDS 32768
#define NB 512              // grid size; co-resident (>= guaranteed by launch_bounds)
#define TPB 256

// ---- device scratch (allocation-free). Reset by finalize each replay. ----
__device__ unsigned g_posbits[NWORDS];
__device__ unsigned g_t1bits[NWORDS];
__device__ double g_ce;
__device__ int    g_hard_i, g_t_i, g_inter_i;
__device__ double g_res[BB];
__device__ int    g_haspos[BB];
__device__ int    g_hasneg[BB];
__device__ unsigned g_bar1;
__device__ unsigned g_bar2;

// ---------------------------------------------------------------------------
// Exact fallback (now ~never taken: P ~ 2^-24 per target pixel)
// ---------------------------------------------------------------------------
__device__ __forceinline__ int row_mindx(const unsigned* __restrict__ row, int j, unsigned inv) {
    int wj = j >> 5, off = j & 31;
    int best = 30000;
    unsigned m = (row[wj] ^ inv) >> off;
    if (m) best = __ffs(m) - 1;
    else {
        for (int w = wj + 1; w < WPR; ++w) {
            unsigned x = row[w] ^ inv;
            if (x) { best = 32 * (w - wj) - off + __ffs(x) - 1; break; }
        }
    }
    unsigned ml = (row[wj] ^ inv) << (31 - off);
    if (ml) { int d = __clz(ml); best = min(best, d); }
    else {
        for (int w = wj - 1; w >= 0; --w) {
            unsigned x = row[w] ^ inv;
            if (x) { int d = j - (32 * w + 31 - __clz(x)); best = min(best, d); break; }
        }
    }
    return best;
}

__device__ double fb_contrib(const unsigned* __restrict__ bp, int i, int j, int mybit,
                             int haspos, int hasneg) {
    float d;
    if (!haspos || !hasneg) {
        d = 1.0e9f;                      // reference BIG: no opposite class exists
    } else {
        unsigned inv = mybit ? 0xffffffffu : 0u;
        int best2 = 1 << 30;
        for (int dy = 0; dy < 256; ++dy) {
            int dy2 = dy * dy;
            if (dy2 >= best2) break;
            int up = i - dy, dn = i + dy;
            if (up >= 0) {
                int dx = row_mindx(bp + up * WPR, j, inv);
                int d2 = dy2 + dx * dx;
                if (d2 < best2) best2 = d2;
            }
            if (dy && dn < 256) {
                int dx = row_mindx(bp + dn * WPR, j, inv);
                int d2 = dy2 + dx * dx;
                if (d2 < best2) best2 = d2;
            }
        }
        d = sqrtf((float)best2);
    }
    return mybit ? -(double)(d - 1.0f) : (double)d;
}

// ---------------------------------------------------------------------------
// Single fused kernel: prep -> grid barrier -> 5x5 bit-parallel boundary
// ---------------------------------------------------------------------------
__global__ __launch_bounds__(TPB, 4)
void k_fused(const float* __restrict__ inp, const int* __restrict__ tgt,
             float* __restrict__ out, int out_size) {
    int tid = threadIdx.x;
    int gt  = blockIdx.x * TPB + tid;

    // ================= Phase 1: bitboards + CE + dice ======================
    {
        int px = gt * 8;
        int b  = px >> 16;                 // block spans 2048 px: one sample
        int hw = px & 65535;

        const float* p0 = inp + (size_t)(b * 2    ) * HW + hw;
        const float* p1 = inp + (size_t)(b * 2 + 1) * HW + hw;
        float4 a0 = *(const float4*)(p0);
        float4 a1 = *(const float4*)(p0 + 4);
        float4 c0 = *(const float4*)(p1);
        float4 c1 = *(const float4*)(p1 + 4);
        int4  t0  = *(const int4*)(tgt + px);
        int4  t1v = *(const int4*)(tgt + px + 4);

        float ces = 0.0f;
        int hard = 0, tcnt = 0, inter = 0;
        unsigned pbyte = 0, tbyte = 0;

        #define ELEM(K, X0, X1, T) {                                   \
            float x0 = (X0), x1 = (X1); int t = (T);                   \
            float m   = fmaxf(x0, x1);                                 \
            float lse = m + __logf(1.0f + __expf(-fabsf(x1 - x0)));    \
            ces += lse - ((t == 1) ? x1 : x0);                         \
            int h  = (x1 >= x0);                                       \
            int tt = (t == 1);                                         \
            hard += h; tcnt += tt; inter += (h & tt);                  \
            pbyte |= ((unsigned)(x1 > x0)) << (K);                     \
            tbyte |= ((unsigned)tt) << (K); }

        ELEM(0, a0.x, c0.x, t0.x)  ELEM(1, a0.y, c0.y, t0.y)
        ELEM(2, a0.z, c0.z, t0.z)  ELEM(3, a0.w, c0.w, t0.w)
        ELEM(4, a1.x, c1.x, t1v.x) ELEM(5, a1.y, c1.y, t1v.y)
        ELEM(6, a1.z, c1.z, t1v.z) ELEM(7, a1.w, c1.w, t1v.w)
        #undef ELEM

        __shared__ unsigned char by_p[TPB], by_t[TPB];
        by_p[tid] = (unsigned char)pbyte;
        by_t[tid] = (unsigned char)tbyte;

        // f32 warp reduce for CE; int reduces for counts
        int p1c = hard | (tcnt << 16);
        int flags = (pbyte ? 1 : 0) | ((pbyte != 0xffu) ? 2 : 0);
        #pragma unroll
        for (int off = 16; off > 0; off >>= 1) {
            ces   += __shfl_xor_sync(0xffffffffu, ces, off);
            p1c   += __shfl_xor_sync(0xffffffffu, p1c, off);
            inter += __shfl_xor_sync(0xffffffffu, inter, off);
            flags |= __shfl_xor_sync(0xffffffffu, flags, off);
        }
        __shared__ float s_ce[8];
        __shared__ int   s_p1[8], s_in[8], s_fl[8];
        int wid = tid >> 5;
        if ((tid & 31) == 0) { s_ce[wid] = ces; s_p1[wid] = p1c; s_in[wid] = inter; s_fl[wid] = flags; }
        __syncthreads();

        if (tid < 128) {
            int w = tid & 63;
            const unsigned char* nb = (tid < 64) ? by_p : by_t;
            unsigned v =  (unsigned)nb[4*w]
                       | ((unsigned)nb[4*w+1] << 8)
                       | ((unsigned)nb[4*w+2] << 16)
                       | ((unsigned)nb[4*w+3] << 24);
            unsigned* dst = (tid < 64) ? g_posbits : g_t1bits;
            dst[blockIdx.x * 64 + w] = v;
        }

        if (tid == 0) {
            double bce = 0.0; int bp1 = 0, bin = 0, bfl = 0;
            #pragma unroll
            for (int w = 0; w < 8; ++w) { bce += (double)s_ce[w]; bp1 += s_p1[w]; bin += s_in[w]; bfl |= s_fl[w]; }
            atomicAdd(&g_ce, bce);
            atomicAdd(&g_hard_i,  bp1 & 0xffff);
            atomicAdd(&g_t_i,     bp1 >> 16);
            atomicAdd(&g_inter_i, bin);
            if (bfl & 1) g_haspos[b] = 1;
            if (bfl & 2) g_hasneg[b] = 1;
        }
    }

    // ================= Grid barrier ========================================
    __syncthreads();
    if (tid == 0) {
        __threadfence();
        atomicAdd(&g_bar1, 1u);
        while (*((volatile unsigned*)&g_bar1) < NB) __nanosleep(64);
        __threadfence();
    }
    __syncthreads();

    // ================= Phase 2: 5x5 bit-parallel boundary ==================
    double contrib = 0.0;
    int wb = blockIdx.x * 64;
    int b2 = wb >> 11;
    if (tid < 64) {
        int w  = (wb + tid) & 2047;
        int i  = w >> 3;
        int wc = w & 7;
        const unsigned* __restrict__ bp = g_posbits + b2 * WPS;
        const unsigned* __restrict__ tp = g_t1bits  + b2 * WPS;

        unsigned lm1 = (wc == 0) ? 0xfffffffeu : 0xffffffffu;
        unsigned rm1 = (wc == 7) ? 0x7fffffffu : 0xffffffffu;
        unsigned lm2 = (wc == 0) ? 0xfffffffcu : 0xffffffffu;
        unsigned rm2 = (wc == 7) ? 0x3fffffffu : 0xffffffffu;
        unsigned vu1 = (i >= 1)   ? 0xffffffffu : 0u;
        unsigned vu2 = (i >= 2)   ? 0xffffffffu : 0u;
        unsigned vd1 = (i <= 254) ? 0xffffffffu : 0u;
        unsigned vd2 = (i <= 253) ? 0xffffffffu : 0u;
        int iu1 = max(i - 1, 0), iu2 = max(i - 2, 0);
        int id1 = min(i + 1, 255), id2 = min(i + 2, 255);

        unsigned P  = bp[i * WPR + wc];
        unsigned T1 = tp[i * WPR + wc];

        // per-row: load L,M,R; produce XOR-with-P masks for shift 0,±1,±2
        #define ROWX(r, XM, X1L, X1R, X2L, X2R) {                        \
            unsigned Lw = (wc > 0) ? bp[(r) * WPR + wc - 1] : 0u;        \
            unsigned Mw = bp[(r) * WPR + wc];                            \
            unsigned Rw = (wc < 7) ? bp[(r) * WPR + wc + 1] : 0u;        \
            XM  = Mw ^ P;                                                \
            X1L = __funnelshift_l(Lw, Mw, 1) ^ P;                        \
            X1R = __funnelshift_r(Mw, Rw, 1) ^ P;                        \
            X2L = __funnelshift_l(Lw, Mw, 2) ^ P;                        \
            X2R = __funnelshift_r(Mw, Rw, 2) ^ P; }

        unsigned m0, l10, r10, l20, r20;   ROWX(i,   m0, l10, r10, l20, r20)
        unsigned mu1, l1u1, r1u1, l2u1, r2u1; ROWX(iu1, mu1, l1u1, r1u1, l2u1, r2u1)
        unsigned md1, l1d1, r1d1, l2d1, r2d1; ROWX(id1, md1, l1d1, r1d1, l2d1, r2d1)
        unsigned mu2, l1u2, r1u2, l2u2, r2u2; ROWX(iu2, mu2, l1u2, r1u2, l2u2, r2u2)
        unsigned md2, l1d2, r1d2, l2d2, r2d2; ROWX(id2, md2, l1d2, r1d2, l2d2, r2d2)
        #undef ROWX

        unsigned D1 = (l10 & lm1) | (r10 & rm1) | (mu1 & vu1) | (md1 & vd1);
        unsigned D2 = (((l1u1 & lm1) | (r1u1 & rm1)) & vu1)
                    | (((l1d1 & lm1) | (r1d1 & rm1)) & vd1);
        unsigned D4 = (l20 & lm2) | (r20 & rm2) | (mu2 & vu2) | (md2 & vd2);
        unsigned D5 = (((l2u1 & lm2) | (r2u1 & rm2)) & vu1)
                    | (((l2d1 & lm2) | (r2d1 & rm2)) & vd1)
                    | (((l1u2 & lm1) | (r1u2 & rm1)) & vu2)
                    | (((l1d2 & lm1) | (r1d2 & rm1)) & vd2);
        unsigned D8 = (((l2u2 & lm2) | (r2u2 & rm2)) & vu2)
                    | (((l2d2 & lm2) | (r2d2 & rm2)) & vd2);

        unsigned A1 = D1 & T1;
        unsigned R2 = T1 & ~D1;   unsigned A2 = D2 & R2;
        unsigned R4 = R2 & ~D2;   unsigned A4 = D4 & R4;
        unsigned R5 = R4 & ~D4;   unsigned A5 = D5 & R5;
        unsigned R8 = R5 & ~D5;   unsigned A8 = D8 & R8;
        unsigned U  = R8 & ~D8;

        // f32-rounded sqrt values (match reference f32 sqrt)
        const double S2 = (double)1.41421354f;
        const double S5 = (double)2.23606801f;
        const double S8 = (double)2.82842708f;

        contrib  = (double)__popc(A1 & ~P);                            // d=1: pos term is 0
        contrib += (double)__popc(A2 & ~P) * S2 - (double)__popc(A2 & P) * (S2 - 1.0);
        contrib += (double)__popc(A4 & ~P) * 2.0 - (double)__popc(A4 & P) * 1.0;
        contrib += (double)__popc(A5 & ~P) * S5 - (double)__popc(A5 & P) * (S5 - 1.0);
        contrib += (double)__popc(A8 & ~P) * S8 - (double)__popc(A8 & P) * (S8 - 1.0);

        if (U) {   // ~2^-24 per pixel: essentially never
            int haspos = g_haspos[b2], hasneg = g_hasneg[b2];
            do {
                int jb = __ffs(U) - 1; U &= U - 1;
                int j = wc * 32 + jb;
                int mybit = (P >> jb) & 1;
                contrib += fb_contrib(bp, i, j, mybit, haspos, hasneg);
            } while (U);
        }
    }

    #pragma unroll
    for (int off = 16; off > 0; off >>= 1)
        contrib += __shfl_xor_sync(0xffffffffu, contrib, off);
    __shared__ double s_c[2];
    if (tid == 0)  s_c[0] = contrib;
    if (tid == 32) s_c[1] = contrib;
    __syncthreads();

    __shared__ bool s_last;
    if (tid == 0) {
        atomicAdd(&g_res[b2], s_c[0] + s_c[1]);
        __threadfence();
        unsigned tk = atomicAdd(&g_bar2, 1u);
        s_last = (tk == NB - 1);
    }
    __syncthreads();

    if (s_last && tid == 0) {
        double ce = g_ce / (double)NPIX;
        double dice = 1.0 - (2.0 * (double)g_inter_i + 1.0)
                          / ((double)g_hard_i + (double)g_t_i + 1.0);
        double lb = 0.0;
        #pragma unroll
        for (int s = 0; s < BB; ++s)
            if (g_haspos[s]) lb += g_res[s] / (double)HW;
        float r = (float)(ce + dice + lb * lb);
        for (int k = 0; k < out_size; ++k) out[k] = r;

        g_ce = 0.0; g_hard_i = 0; g_t_i = 0; g_inter_i = 0;
        #pragma unroll
        for (int s = 0; s < BB; ++s) { g_res[s] = 0.0; g_haspos[s] = 0; g_hasneg[s] = 0; }
        g_bar1 = 0u; g_bar2 = 0u;
    }
}

extern "C" void kernel_launch(void* const* d_in, const int* in_sizes, int n_in,
                              void* d_out, int out_size) {
    const float* inputs  = (const float*)d_in[0];   // (16,2,256,256) f32
    const int*   targets = (const int*)  d_in[1];   // (16,256,256)   i32
    k_fused<<<NB, TPB>>>(inputs, targets, (float*)d_out, out_size);
}

// round 6
// speedup vs baseline: 1.4068x; 1.1356x over previous
#include <cuda_runtime.h>
#include <math.h>

#define BB 16
#define HW 65536            // 256*256
#define NPIX (BB*HW)        // 1048576
#define WPR 8               // u32 words per row
#define WPS 2048            // words per sample
#define NWORDS 32768
#define NB 512              // 16 samples * 32 row-groups
#define TPB 256
#define WLCAP 32768

// ---- device scratch (allocation-free). Reset by final block each replay. ----
__device__ unsigned g_posbits[NWORDS];
__device__ double g_ce;
__device__ int    g_hard_i, g_t_i, g_inter_i;
__device__ double g_res[BB];
__device__ int    g_haspos[BB];
__device__ int    g_hasneg[BB];
__device__ unsigned g_ticket;
__device__ int    g_wl_n;
__device__ int    g_wl[WLCAP];

// ---------------------------------------------------------------------------
// Exact fallback (P ~ 2^-24 per target pixel; runs in final block only)
// ---------------------------------------------------------------------------
__device__ __forceinline__ int row_mindx(const unsigned* __restrict__ row, int j, unsigned inv) {
    int wj = j >> 5, off = j & 31;
    int best = 30000;
    unsigned m = (row[wj] ^ inv) >> off;
    if (m) best = __ffs(m) - 1;
    else {
        for (int w = wj + 1; w < WPR; ++w) {
            unsigned x = row[w] ^ inv;
            if (x) { best = 32 * (w - wj) - off + __ffs(x) - 1; break; }
        }
    }
    unsigned ml = (row[wj] ^ inv) << (31 - off);
    if (ml) { int d = __clz(ml); best = min(best, d); }
    else {
        for (int w = wj - 1; w >= 0; --w) {
            unsigned x = row[w] ^ inv;
            if (x) { int d = j - (32 * w + 31 - __clz(x)); best = min(best, d); break; }
        }
    }
    return best;
}

__device__ double fb_contrib(const unsigned* __restrict__ bp, int i, int j, int mybit,
                             int haspos, int hasneg) {
    float d;
    if (!haspos || !hasneg) {
        d = 1.0e9f;                      // reference BIG
    } else {
        unsigned inv = mybit ? 0xffffffffu : 0u;
        int best2 = 1 << 30;
        for (int dy = 0; dy < 256; ++dy) {
            int dy2 = dy * dy;
            if (dy2 >= best2) break;
            int up = i - dy, dn = i + dy;
            if (up >= 0) {
                int dx = row_mindx(bp + up * WPR, j, inv);
                int d2 = dy2 + dx * dx;
                if (d2 < best2) best2 = d2;
            }
            if (dy && dn < 256) {
                int dx = row_mindx(bp + dn * WPR, j, inv);
                int d2 = dy2 + dx * dx;
                if (d2 < best2) best2 = d2;
            }
        }
        d = sqrtf((float)best2);
    }
    return mybit ? -(double)(d - 1.0f) : (double)d;
}

// ---------------------------------------------------------------------------
// One kernel, no grid barrier: each block owns 8 rows + 4 halo rows in SMEM.
// ---------------------------------------------------------------------------
__global__ __launch_bounds__(TPB)
void k_fused(const float* __restrict__ inp, const int* __restrict__ tgt,
             float* __restrict__ out, int out_size) {
    __shared__ unsigned char sh_pb[12 * 32];   // 12 rows x 32 pos-bytes
    __shared__ unsigned char sh_tb[8 * 32];    // 8 main rows x 32 t1-bytes
    __shared__ unsigned sh_pw[12 * 8];         // pos words
    __shared__ unsigned sh_tw[8 * 8];          // t1 words
    __shared__ float  s_ce[8];
    __shared__ int    s_p1[8], s_in[8], s_fl[8];
    __shared__ double s_c[2];
    __shared__ bool   s_last;

    int tid = threadIdx.x;
    int blk = blockIdx.x;
    int s   = blk >> 5;            // sample
    int r0  = (blk & 31) << 3;     // first of the 8 main rows

    // ---------------- Phase 1: main rows (8 px/thread) --------------------
    int row_local = tid >> 5;      // 0..7
    int cb        = tid & 31;      // byte (8-px group) within row
    int absrow    = r0 + row_local;
    size_t moff   = (size_t)s * HW + absrow * 256 + cb * 8;

    const float* p0 = inp + (size_t)(s * 2) * HW + (absrow * 256 + cb * 8);
    const float* p1 = p0 + HW;
    float4 a0 = *(const float4*)(p0);
    float4 a1 = *(const float4*)(p0 + 4);
    float4 c0 = *(const float4*)(p1);
    float4 c1 = *(const float4*)(p1 + 4);
    int4  t0  = *(const int4*)(tgt + moff);
    int4  t1v = *(const int4*)(tgt + moff + 4);

    // halo loads issued early (threads 0..127: 4 halo rows x 32 byte-groups)
    float4 h0a, h0b, h1a, h1b;
    int hvalid = 0, hrow12 = 0, hcb = tid & 31;
    if (tid < 128) {
        int hr   = tid >> 5;                              // 0..3
        int habs = (hr < 2) ? (r0 - 2 + hr) : (r0 + 8 + (hr - 2));
        hrow12   = (hr < 2) ? hr : (10 + (hr - 2));
        hvalid   = (habs >= 0 && habs <= 255);
        if (hvalid) {
            const float* q0 = inp + (size_t)(s * 2) * HW + (habs * 256 + hcb * 8);
            const float* q1 = q0 + HW;
            h0a = *(const float4*)(q0);
            h0b = *(const float4*)(q0 + 4);
            h1a = *(const float4*)(q1);
            h1b = *(const float4*)(q1 + 4);
        }
    }

    float ces = 0.0f;
    int hard = 0, tcnt = 0, inter = 0;
    unsigned pbyte = 0, tbyte = 0;

    #define ELEM(K, X0, X1, T) {                                   \
        float x0 = (X0), x1 = (X1); int t = (T);                   \
        float m   = fmaxf(x0, x1);                                 \
        float lse = m + __logf(1.0f + __expf(-fabsf(x1 - x0)));    \
        ces += lse - ((t == 1) ? x1 : x0);                         \
        int h  = (x1 >= x0);                                       \
        int tt = (t == 1);                                         \
        hard += h; tcnt += tt; inter += (h & tt);                  \
        pbyte |= ((unsigned)(x1 > x0)) << (K);                     \
        tbyte |= ((unsigned)tt) << (K); }

    ELEM(0, a0.x, c0.x, t0.x)  ELEM(1, a0.y, c0.y, t0.y)
    ELEM(2, a0.z, c0.z, t0.z)  ELEM(3, a0.w, c0.w, t0.w)
    ELEM(4, a1.x, c1.x, t1v.x) ELEM(5, a1.y, c1.y, t1v.y)
    ELEM(6, a1.z, c1.z, t1v.z) ELEM(7, a1.w, c1.w, t1v.w)
    #undef ELEM

    sh_pb[(row_local + 2) * 32 + cb] = (unsigned char)pbyte;
    sh_tb[row_local * 32 + cb]       = (unsigned char)tbyte;

    // halo pos-bytes
    if (tid < 128) {
        unsigned hpb = 0;
        if (hvalid) {
            hpb |= ((unsigned)(h1a.x > h0a.x)) << 0;
            hpb |= ((unsigned)(h1a.y > h0a.y)) << 1;
            hpb |= ((unsigned)(h1a.z > h0a.z)) << 2;
            hpb |= ((unsigned)(h1a.w > h0a.w)) << 3;
            hpb |= ((unsigned)(h1b.x > h0b.x)) << 4;
            hpb |= ((unsigned)(h1b.y > h0b.y)) << 5;
            hpb |= ((unsigned)(h1b.z > h0b.z)) << 6;
            hpb |= ((unsigned)(h1b.w > h0b.w)) << 7;
        }
        sh_pb[hrow12 * 32 + hcb] = (unsigned char)hpb;
    }

    // warp reductions (f32 CE, packed counts, class flags)
    int p1c = hard | (tcnt << 16);
    int flags = (pbyte ? 1 : 0) | ((pbyte != 0xffu) ? 2 : 0);
    #pragma unroll
    for (int off = 16; off > 0; off >>= 1) {
        ces   += __shfl_xor_sync(0xffffffffu, ces, off);
        p1c   += __shfl_xor_sync(0xffffffffu, p1c, off);
        inter += __shfl_xor_sync(0xffffffffu, inter, off);
        flags |= __shfl_xor_sync(0xffffffffu, flags, off);
    }
    int wid = tid >> 5;
    if ((tid & 31) == 0) { s_ce[wid] = ces; s_p1[wid] = p1c; s_in[wid] = inter; s_fl[wid] = flags; }
    __syncthreads();

    // word assembly + block-level atomics
    if (tid < 96) {
        unsigned v =  (unsigned)sh_pb[4*tid]
                   | ((unsigned)sh_pb[4*tid+1] << 8)
                   | ((unsigned)sh_pb[4*tid+2] << 16)
                   | ((unsigned)sh_pb[4*tid+3] << 24);
        sh_pw[tid] = v;
    } else if (tid < 160) {
        int k = tid - 96;
        unsigned v =  (unsigned)sh_tb[4*k]
                   | ((unsigned)sh_tb[4*k+1] << 8)
                   | ((unsigned)sh_tb[4*k+2] << 16)
                   | ((unsigned)sh_tb[4*k+3] << 24);
        sh_tw[k] = v;
    }
    if (tid == 0) {
        double bce = 0.0; int bp1 = 0, bin = 0, bfl = 0;
        #pragma unroll
        for (int w = 0; w < 8; ++w) { bce += (double)s_ce[w]; bp1 += s_p1[w]; bin += s_in[w]; bfl |= s_fl[w]; }
        atomicAdd(&g_ce, bce);
        atomicAdd(&g_hard_i,  bp1 & 0xffff);
        atomicAdd(&g_t_i,     bp1 >> 16);
        atomicAdd(&g_inter_i, bin);
        if (bfl & 1) g_haspos[s] = 1;
        if (bfl & 2) g_hasneg[s] = 1;
    }
    __syncthreads();

    // ---------------- Phase 2: 5x5 bit-parallel, SMEM-local ----------------
    double contrib = 0.0;
    if (tid < 64) {
        int wr = tid >> 3;           // main row 0..7
        int wc = tid & 7;
        int i  = r0 + wr;            // absolute row
        int i12 = wr + 2;            // row in shared window

        // write global bitboard (fallback path only)
        g_posbits[s * WPS + i * WPR + wc] = sh_pw[i12 * 8 + wc];

        unsigned P  = sh_pw[i12 * 8 + wc];
        unsigned T1 = sh_tw[wr * 8 + wc];

        unsigned lm1 = (wc == 0) ? 0xfffffffeu : 0xffffffffu;
        unsigned rm1 = (wc == 7) ? 0x7fffffffu : 0xffffffffu;
        unsigned lm2 = (wc == 0) ? 0xfffffffcu : 0xffffffffu;
        unsigned rm2 = (wc == 7) ? 0x3fffffffu : 0xffffffffu;
        unsigned vu1 = (i >= 1)   ? 0xffffffffu : 0u;
        unsigned vu2 = (i >= 2)   ? 0xffffffffu : 0u;
        unsigned vd1 = (i <= 254) ? 0xffffffffu : 0u;
        unsigned vd2 = (i <= 253) ? 0xffffffffu : 0u;

        #define ROWX(r12, XM, X1L, X1R, X2L, X2R) {                      \
            unsigned Lw = (wc > 0) ? sh_pw[(r12) * 8 + wc - 1] : 0u;     \
            unsigned Mw = sh_pw[(r12) * 8 + wc];                         \
            unsigned Rw = (wc < 7) ? sh_pw[(r12) * 8 + wc + 1] : 0u;     \
            XM  = Mw ^ P;                                                \
            X1L = __funnelshift_l(Lw, Mw, 1) ^ P;                        \
            X1R = __funnelshift_r(Mw, Rw, 1) ^ P;                        \
            X2L = __funnelshift_l(Lw, Mw, 2) ^ P;                        \
            X2R = __funnelshift_r(Mw, Rw, 2) ^ P; }

        unsigned m0, l10, r10, l20, r20;      ROWX(i12,     m0,  l10,  r10,  l20,  r20)
        unsigned mu1, l1u1, r1u1, l2u1, r2u1; ROWX(i12 - 1, mu1, l1u1, r1u1, l2u1, r2u1)
        unsigned md1, l1d1, r1d1, l2d1, r2d1; ROWX(i12 + 1, md1, l1d1, r1d1, l2d1, r2d1)
        unsigned mu2, l1u2, r1u2, l2u2, r2u2; ROWX(i12 - 2, mu2, l1u2, r1u2, l2u2, r2u2)
        unsigned md2, l1d2, r1d2, l2d2, r2d2; ROWX(i12 + 2, md2, l1d2, r1d2, l2d2, r2d2)
        #undef ROWX

        unsigned D1 = (l10 & lm1) | (r10 & rm1) | (mu1 & vu1) | (md1 & vd1);
        unsigned D2 = (((l1u1 & lm1) | (r1u1 & rm1)) & vu1)
                    | (((l1d1 & lm1) | (r1d1 & rm1)) & vd1);
        unsigned D4 = (l20 & lm2) | (r20 & rm2) | (mu2 & vu2) | (md2 & vd2);
        unsigned D5 = (((l2u1 & lm2) | (r2u1 & rm2)) & vu1)
                    | (((l2d1 & lm2) | (r2d1 & rm2)) & vd1)
                    | (((l1u2 & lm1) | (r1u2 & rm1)) & vu2)
                    | (((l1d2 & lm1) | (r1d2 & rm1)) & vd2);
        unsigned D8 = (((l2u2 & lm2) | (r2u2 & rm2)) & vu2)
                    | (((l2d2 & lm2) | (r2d2 & rm2)) & vd2);

        unsigned A1 = D1 & T1;
        unsigned R2 = T1 & ~D1;   unsigned A2 = D2 & R2;
        unsigned R4 = R2 & ~D2;   unsigned A4 = D4 & R4;
        unsigned R5 = R4 & ~D4;   unsigned A5 = D5 & R5;
        unsigned R8 = R5 & ~D5;   unsigned A8 = D8 & R8;
        unsigned U  = R8 & ~D8;

        const double S2 = (double)1.41421354f;
        const double S5 = (double)2.23606801f;
        const double S8 = (double)2.82842708f;

        contrib  = (double)__popc(A1 & ~P);
        contrib += (double)__popc(A2 & ~P) * S2 - (double)__popc(A2 & P) * (S2 - 1.0);
        contrib += (double)__popc(A4 & ~P) * 2.0 - (double)__popc(A4 & P) * 1.0;
        contrib += (double)__popc(A5 & ~P) * S5 - (double)__popc(A5 & P) * (S5 - 1.0);
        contrib += (double)__popc(A8 & ~P) * S8 - (double)__popc(A8 & P) * (S8 - 1.0);

        while (U) {   // ~never: defer to worklist for the final block
            int jb = __ffs(U) - 1; U &= U - 1;
            int j = wc * 32 + jb;
            int mybit = (P >> jb) & 1;
            int slot = atomicAdd(&g_wl_n, 1);
            if (slot < WLCAP)
                g_wl[slot] = (s << 17) | (i << 9) | (j << 1) | mybit;
        }

        #pragma unroll
        for (int off = 16; off > 0; off >>= 1)
            contrib += __shfl_xor_sync(0xffffffffu, contrib, off);
        if (tid == 0)  s_c[0] = contrib;
        if (tid == 32) s_c[1] = contrib;
    }
    __syncthreads();

    if (tid == 0) {
        atomicAdd(&g_res[s], s_c[0] + s_c[1]);
        __threadfence();
        unsigned tk = atomicAdd(&g_ticket, 1u);
        s_last = (tk == NB - 1);
    }
    __syncthreads();

    // ---------------- Final block: worklist + finalize ----------------------
    if (s_last) {
        if (tid == 0) __threadfence();
        __syncthreads();
        int n = g_wl_n; if (n > WLCAP) n = WLCAP;
        for (int k = tid; k < n; k += TPB) {
            int e = g_wl[k];
            int es = e >> 17, ei = (e >> 9) & 255, ej = (e >> 1) & 255, eb = e & 1;
            double v = fb_contrib(g_posbits + es * WPS, ei, ej, eb,
                                  g_haspos[es], g_hasneg[es]);
            atomicAdd(&g_res[es], v);
        }
        __syncthreads();
        if (tid == 0) {
            double ce = g_ce / (double)NPIX;
            double dice = 1.0 - (2.0 * (double)g_inter_i + 1.0)
                              / ((double)g_hard_i + (double)g_t_i + 1.0);
            double lb = 0.0;
            #pragma unroll
            for (int q = 0; q < BB; ++q)
                if (g_haspos[q]) lb += g_res[q] / (double)HW;
            float r = (float)(ce + dice + lb * lb);
            for (int k = 0; k < out_size; ++k) out[k] = r;

            g_ce = 0.0; g_hard_i = 0; g_t_i = 0; g_inter_i = 0;
            #pragma unroll
            for (int q = 0; q < BB; ++q) { g_res[q] = 0.0; g_haspos[q] = 0; g_hasneg[q] = 0; }
            g_ticket = 0u; g_wl_n = 0;
        }
    }
}

extern "C" void kernel_launch(void* const* d_in, const int* in_sizes, int n_in,
                              void* d_out, int out_size) {
    const float* inputs  = (const float*)d_in[0];   // (16,2,256,256) f32
    const int*   targets = (const int*)  d_in[1];   // (16,256,256)   i32
    k_fused<<<NB, TPB>>>(inputs, targets, (float*)d_out, out_size);
}

// round 7
// speedup vs baseline: 1.6275x; 1.1569x over previous
#include <cuda_runtime.h>
#include <math.h>

#define BB 16
#define HW 65536            // 256*256
#define NPIX (BB*HW)        // 1048576
#define WPR 8               // u32 words per row
#define WPS 2048            // words per sample
#define NWORDS 32768
#define NB 512              // 16 samples * 32 row-groups (8 rows each)
#define TPB 128
#define WLCAP 65536

// ---- device scratch (allocation-free). Reset by final block each replay. ----
__device__ unsigned g_posbits[NWORDS];
__device__ double g_ce;
__device__ int    g_hard_i, g_t_i, g_inter_i;
__device__ double g_res[BB];
__device__ int    g_haspos[BB];
__device__ int    g_hasneg[BB];
__device__ unsigned g_ticket;
__device__ int    g_wl_n;
__device__ int    g_wl[WLCAP];

// ---------------------------------------------------------------------------
// Exact fallback (P ~ 2^-24 per target pixel; runs in final block only)
// ---------------------------------------------------------------------------
__device__ __forceinline__ int row_mindx(const unsigned* __restrict__ row, int j, unsigned inv) {
    int wj = j >> 5, off = j & 31;
    int best = 30000;
    unsigned m = (row[wj] ^ inv) >> off;
    if (m) best = __ffs(m) - 1;
    else {
        for (int w = wj + 1; w < WPR; ++w) {
            unsigned x = row[w] ^ inv;
            if (x) { best = 32 * (w - wj) - off + __ffs(x) - 1; break; }
        }
    }
    unsigned ml = (row[wj] ^ inv) << (31 - off);
    if (ml) { int d = __clz(ml); best = min(best, d); }
    else {
        for (int w = wj - 1; w >= 0; --w) {
            unsigned x = row[w] ^ inv;
            if (x) { int d = j - (32 * w + 31 - __clz(x)); best = min(best, d); break; }
        }
    }
    return best;
}

__device__ double fb_contrib(const unsigned* __restrict__ bp, int i, int j, int mybit,
                             int haspos, int hasneg) {
    float d;
    if (!haspos || !hasneg) {
        d = 1.0e9f;                      // reference BIG
    } else {
        unsigned inv = mybit ? 0xffffffffu : 0u;
        int best2 = 1 << 30;
        for (int dy = 0; dy < 256; ++dy) {
            int dy2 = dy * dy;
            if (dy2 >= best2) break;
            int up = i - dy, dn = i + dy;
            if (up >= 0) {
                int dx = row_mindx(bp + up * WPR, j, inv);
                int d2 = dy2 + dx * dx;
                if (d2 < best2) best2 = d2;
            }
            if (dy && dn < 256) {
                int dx = row_mindx(bp + dn * WPR, j, inv);
                int d2 = dy2 + dx * dx;
                if (d2 < best2) best2 = d2;
            }
        }
        d = sqrtf((float)best2);
    }
    return mybit ? -(double)(d - 1.0f) : (double)d;
}

// ---------------------------------------------------------------------------
// One kernel, 128 threads/block, 16 px/thread + halo, SMEM-local phase 2.
// ---------------------------------------------------------------------------
__global__ __launch_bounds__(TPB)
void k_fused(const float* __restrict__ inp, const int* __restrict__ tgt,
             float* __restrict__ out, int out_size) {
    __shared__ unsigned short sh_ph16[8 * 16];   // main pos bits (16/thread)
    __shared__ unsigned short sh_th16[8 * 16];   // main t1 bits
    __shared__ unsigned char  sh_hb[4 * 32];     // halo pos bytes
    __shared__ unsigned sh_pw[12 * 8];           // 12 rows x 8 words
    __shared__ unsigned sh_tw[8 * 8];
    __shared__ float  s_ce[4];
    __shared__ int    s_cnt[4], s_fl[4];
    __shared__ float  s_c[2];
    __shared__ bool   s_last;

    int tid = threadIdx.x;
    int blk = blockIdx.x;
    int s   = blk >> 5;            // sample
    int r0  = (blk & 31) << 3;     // first main row

    // ---------------- Phase 1: 16 px/thread main + 8 px halo --------------
    int row_local = tid >> 4;      // 0..7
    int grp       = tid & 15;      // 16-px group
    int absrow    = r0 + row_local;
    size_t moff   = (size_t)s * HW + absrow * 256 + grp * 16;

    const float* p0 = inp + (size_t)(s * 2) * HW + (absrow * 256 + grp * 16);
    const float* p1 = p0 + HW;

    float4 A[4], C[4]; int4 T[4];
    #pragma unroll
    for (int q = 0; q < 4; ++q) {
        A[q] = *(const float4*)(p0 + 4 * q);
        C[q] = *(const float4*)(p1 + 4 * q);
        T[q] = *(const int4*)(tgt + moff + 4 * q);
    }

    // halo loads (8 px each thread): rows r0-2, r0-1, r0+8, r0+9
    int hr = tid >> 5, hcb = tid & 31;
    int habs = (hr < 2) ? (r0 - 2 + hr) : (r0 + 8 + (hr - 2));
    int hvalid = (habs >= 0 && habs <= 255);
    float4 H0a, H0b, H1a, H1b;
    if (hvalid) {
        const float* q0 = inp + (size_t)(s * 2) * HW + (habs * 256 + hcb * 8);
        H0a = *(const float4*)(q0);
        H0b = *(const float4*)(q0 + 4);
        H1a = *(const float4*)(q0 + HW);
        H1b = *(const float4*)(q0 + HW + 4);
    }

    const float* ax = (const float*)A;
    const float* cx = (const float*)C;
    const int*   tx = (const int*)T;
    float ces = 0.0f;
    int hard = 0, tcnt = 0, inter = 0;
    unsigned pbits = 0, tbits = 0;
    #pragma unroll
    for (int k = 0; k < 16; ++k) {
        float x0 = ax[k], x1 = cx[k]; int t = tx[k];
        float m   = fmaxf(x0, x1);
        float lse = m + __logf(1.0f + __expf(-fabsf(x1 - x0)));
        ces += lse - ((t == 1) ? x1 : x0);
        int h  = (x1 >= x0);
        int tt = (t == 1);
        hard += h; tcnt += tt; inter += (h & tt);
        pbits |= ((unsigned)(x1 > x0)) << k;
        tbits |= ((unsigned)tt) << k;
    }

    sh_ph16[row_local * 16 + grp] = (unsigned short)pbits;
    sh_th16[row_local * 16 + grp] = (unsigned short)tbits;

    unsigned hpb = 0;
    if (hvalid) {
        hpb |= ((unsigned)(H1a.x > H0a.x)) << 0;
        hpb |= ((unsigned)(H1a.y > H0a.y)) << 1;
        hpb |= ((unsigned)(H1a.z > H0a.z)) << 2;
        hpb |= ((unsigned)(H1a.w > H0a.w)) << 3;
        hpb |= ((unsigned)(H1b.x > H0b.x)) << 4;
        hpb |= ((unsigned)(H1b.y > H0b.y)) << 5;
        hpb |= ((unsigned)(H1b.z > H0b.z)) << 6;
        hpb |= ((unsigned)(H1b.w > H0b.w)) << 7;
    }
    sh_hb[hr * 32 + hcb] = (unsigned char)hpb;

    // cheap warp reductions: REDUX for packed counts, ballots for flags
    unsigned cnt = (unsigned)hard | ((unsigned)tcnt << 10) | ((unsigned)inter << 20);
    unsigned wcnt = __reduce_add_sync(0xffffffffu, cnt);
    unsigned bp  = __ballot_sync(0xffffffffu, pbits != 0u);
    unsigned bn  = __ballot_sync(0xffffffffu, pbits != 0xffffu);
    #pragma unroll
    for (int off = 16; off > 0; off >>= 1)
        ces += __shfl_xor_sync(0xffffffffu, ces, off);
    int wid = tid >> 5;
    if ((tid & 31) == 0) {
        s_ce[wid]  = ces;
        s_cnt[wid] = (int)wcnt;
        s_fl[wid]  = (bp ? 1 : 0) | (bn ? 2 : 0);
    }
    __syncthreads();

    // ---------------- word assembly + block atomics ------------------------
    if (tid < 96) {                              // pos words: 12 rows x 8
        int row = tid >> 3, wc = tid & 7;
        unsigned v;
        if (row >= 2 && row <= 9) {
            int mr = row - 2;
            v =  (unsigned)sh_ph16[mr * 16 + 2 * wc]
              | ((unsigned)sh_ph16[mr * 16 + 2 * wc + 1] << 16);
        } else {
            int hrow = (row < 2) ? row : (row - 8);  // 10->2, 11->3
            v =  (unsigned)sh_hb[hrow * 32 + 4 * wc]
              | ((unsigned)sh_hb[hrow * 32 + 4 * wc + 1] << 8)
              | ((unsigned)sh_hb[hrow * 32 + 4 * wc + 2] << 16)
              | ((unsigned)sh_hb[hrow * 32 + 4 * wc + 3] << 24);
        }
        sh_pw[tid] = v;
    }
    if (tid >= 64) {                             // t1 words: 8 rows x 8
        int w = tid - 64;
        int mr = w >> 3, wc = w & 7;
        sh_tw[w] =  (unsigned)sh_th16[mr * 16 + 2 * wc]
                 | ((unsigned)sh_th16[mr * 16 + 2 * wc + 1] << 16);
    }
    if (tid == 0) {
        float bce = 0.0f; int bh = 0, bt = 0, bi = 0, bfl = 0;
        #pragma unroll
        for (int w = 0; w < 4; ++w) {
            bce += s_ce[w];
            unsigned c = (unsigned)s_cnt[w];
            bh += (int)(c & 1023u); bt += (int)((c >> 10) & 1023u); bi += (int)(c >> 20);
            bfl |= s_fl[w];
        }
        atomicAdd(&g_ce, (double)bce);
        atomicAdd(&g_hard_i,  bh);
        atomicAdd(&g_t_i,     bt);
        atomicAdd(&g_inter_i, bi);
        if (bfl & 1) g_haspos[s] = 1;
        if (bfl & 2) g_hasneg[s] = 1;
    }
    __syncthreads();

    // ---------------- Phase 2: 5x5 bit-parallel (64 threads) ---------------
    float contrib = 0.0f;
    if (tid < 64) {
        int wr = tid >> 3, wc = tid & 7;
        int i   = r0 + wr;
        int i12 = wr + 2;

        unsigned P  = sh_pw[i12 * 8 + wc];
        unsigned T1 = sh_tw[wr * 8 + wc];
        g_posbits[s * WPS + i * WPR + wc] = P;   // for worklist fallback only

        unsigned lm1 = (wc == 0) ? 0xfffffffeu : 0xffffffffu;
        unsigned rm1 = (wc == 7) ? 0x7fffffffu : 0xffffffffu;
        unsigned lm2 = (wc == 0) ? 0xfffffffcu : 0xffffffffu;
        unsigned rm2 = (wc == 7) ? 0x3fffffffu : 0xffffffffu;
        unsigned vu1 = (i >= 1)   ? 0xffffffffu : 0u;
        unsigned vu2 = (i >= 2)   ? 0xffffffffu : 0u;
        unsigned vd1 = (i <= 254) ? 0xffffffffu : 0u;
        unsigned vd2 = (i <= 253) ? 0xffffffffu : 0u;

        #define ROWX(r12, XM, X1L, X1R, X2L, X2R) {                      \
            unsigned Lw = (wc > 0) ? sh_pw[(r12) * 8 + wc - 1] : 0u;     \
            unsigned Mw = sh_pw[(r12) * 8 + wc];                         \
            unsigned Rw = (wc < 7) ? sh_pw[(r12) * 8 + wc + 1] : 0u;     \
            XM  = Mw ^ P;                                                \
            X1L = __funnelshift_l(Lw, Mw, 1) ^ P;                        \
            X1R = __funnelshift_r(Mw, Rw, 1) ^ P;                        \
            X2L = __funnelshift_l(Lw, Mw, 2) ^ P;                        \
            X2R = __funnelshift_r(Mw, Rw, 2) ^ P; }

        unsigned m0, l10, r10, l20, r20;      ROWX(i12,     m0,  l10,  r10,  l20,  r20)
        unsigned mu1, l1u1, r1u1, l2u1, r2u1; ROWX(i12 - 1, mu1, l1u1, r1u1, l2u1, r2u1)
        unsigned md1, l1d1, r1d1, l2d1, r2d1; ROWX(i12 + 1, md1, l1d1, r1d1, l2d1, r2d1)
        unsigned mu2, l1u2, r1u2, l2u2, r2u2; ROWX(i12 - 2, mu2, l1u2, r1u2, l2u2, r2u2)
        unsigned md2, l1d2, r1d2, l2d2, r2d2; ROWX(i12 + 2, md2, l1d2, r1d2, l2d2, r2d2)
        #undef ROWX

        unsigned D1 = (l10 & lm1) | (r10 & rm1) | (mu1 & vu1) | (md1 & vd1);
        unsigned D2 = (((l1u1 & lm1) | (r1u1 & rm1)) & vu1)
                    | (((l1d1 & lm1) | (r1d1 & rm1)) & vd1);
        unsigned D4 = (l20 & lm2) | (r20 & rm2) | (mu2 & vu2) | (md2 & vd2);
        unsigned D5 = (((l2u1 & lm2) | (r2u1 & rm2)) & vu1)
                    | (((l2d1 & lm2) | (r2d1 & rm2)) & vd1)
                    | (((l1u2 & lm1) | (r1u2 & rm1)) & vu2)
                    | (((l1d2 & lm1) | (r1d2 & rm1)) & vd2);
        unsigned D8 = (((l2u2 & lm2) | (r2u2 & rm2)) & vu2)
                    | (((l2d2 & lm2) | (r2d2 & rm2)) & vd2);

        unsigned A1m = D1 & T1;
        unsigned R2m = T1 & ~D1;   unsigned A2m = D2 & R2m;
        unsigned R4m = R2m & ~D2;  unsigned A4m = D4 & R4m;
        unsigned R5m = R4m & ~D4;  unsigned A5m = D5 & R5m;
        unsigned R8m = R5m & ~D5;  unsigned A8m = D8 & R8m;
        unsigned U   = R8m & ~D8;

        const float S2 = 1.41421354f;
        const float S5 = 2.23606801f;
        const float S8 = 2.82842708f;

        contrib  = (float)__popc(A1m & ~P);
        contrib += (float)__popc(A2m & ~P) * S2 - (float)__popc(A2m & P) * (S2 - 1.0f);
        contrib += (float)__popc(A4m & ~P) * 2.0f - (float)__popc(A4m & P) * 1.0f;
        contrib += (float)__popc(A5m & ~P) * S5 - (float)__popc(A5m & P) * (S5 - 1.0f);
        contrib += (float)__popc(A8m & ~P) * S8 - (float)__popc(A8m & P) * (S8 - 1.0f);

        while (U) {   // ~never: defer to worklist for the final block
            int jb = __ffs(U) - 1; U &= U - 1;
            int j = wc * 32 + jb;
            int mybit = (P >> jb) & 1;
            int slot = atomicAdd(&g_wl_n, 1);
            if (slot < WLCAP)
                g_wl[slot] = (s << 17) | (i << 9) | (j << 1) | mybit;
        }

        #pragma unroll
        for (int off = 16; off > 0; off >>= 1)
            contrib += __shfl_xor_sync(0xffffffffu, contrib, off);
        if (tid == 0)  s_c[0] = contrib;
        if (tid == 32) s_c[1] = contrib;
    }
    __syncthreads();

    if (tid == 0) {
        atomicAdd(&g_res[s], (double)(s_c[0] + s_c[1]));
        __threadfence();
        unsigned tk = atomicAdd(&g_ticket, 1u);
        s_last = (tk == NB - 1);
    }
    __syncthreads();

    // ---------------- Final block: worklist + finalize ----------------------
    if (s_last) {
        if (tid == 0) __threadfence();
        __syncthreads();
        int n = g_wl_n; if (n > WLCAP) n = WLCAP;
        for (int k = tid; k < n; k += TPB) {
            int e = g_wl[k];
            int es = e >> 17, ei = (e >> 9) & 255, ej = (e >> 1) & 255, eb = e & 1;
            double v = fb_contrib(g_posbits + es * WPS, ei, ej, eb,
                                  g_haspos[es], g_hasneg[es]);
            atomicAdd(&g_res[es], v);
        }
        __syncthreads();
        if (tid == 0) {
            double ce = g_ce / (double)NPIX;
            double dice = 1.0 - (2.0 * (double)g_inter_i + 1.0)
                              / ((double)g_hard_i + (double)g_t_i + 1.0);
            double lb = 0.0;
            #pragma unroll
            for (int q = 0; q < BB; ++q)
                if (g_haspos[q]) lb += g_res[q] / (double)HW;
            float r = (float)(ce + dice + lb * lb);
            for (int k = 0; k < out_size; ++k) out[k] = r;

            g_ce = 0.0; g_hard_i = 0; g_t_i = 0; g_inter_i = 0;
            #pragma unroll
            for (int q = 0; q < BB; ++q) { g_res[q] = 0.0; g_haspos[q] = 0; g_hasneg[q] = 0; }
            g_ticket = 0u; g_wl_n = 0;
        }
    }
}

extern "C" void kernel_launch(void* const* d_in, const int* in_sizes, int n_in,
                              void* d_out, int out_size) {
    const float* inputs  = (const float*)d_in[0];   // (16,2,256,256) f32
    const int*   targets = (const int*)  d_in[1];   // (16,256,256)   i32
    k_fused<<<NB, TPB>>>(inputs, targets, (float*)d_out, out_size);
}